// round 3
// baseline (speedup 1.0000x reference)
#include <cuda_runtime.h>
#include <cuda_bf16.h>

// Problem constants
#define BATCH   4
#define SEQ     2048
#define DMODEL  4096
#define ELOC    512
#define MROWS   (BATCH*SEQ)      // 8192

// GEMM tiling
#define BM 128
#define BN 64
#define BK 16
#define NT 256

// ---------------- scratch (static device arrays; no allocation) -------------
__device__ float g_Q [BATCH*SEQ*ELOC];   // 16.8 MB
__device__ float g_K [BATCH*SEQ*ELOC];
__device__ float g_V [BATCH*SEQ*ELOC];
__device__ float g_S [BATCH*SEQ*SEQ];    // 67 MB (scores / probs)
__device__ float g_AT[BATCH*ELOC*SEQ];   // attention output, e-major (transposed)

// ---------------- f32x2 helpers (packed FFMA2) ------------------------------
__device__ __forceinline__ unsigned long long pack2(float lo, float hi) {
    unsigned long long r;
    asm("mov.b64 %0, {%1, %2};" : "=l"(r) : "f"(lo), "f"(hi));
    return r;
}
__device__ __forceinline__ void unpack2(unsigned long long v, float &lo, float &hi) {
    asm("mov.b64 {%0, %1}, %2;" : "=f"(lo), "=f"(hi) : "l"(v));
}
__device__ __forceinline__ void ffma2(unsigned long long &d,
                                      unsigned long long a,
                                      unsigned long long b) {
    asm("fma.rn.f32x2 %0, %1, %2, %0;" : "+l"(d) : "l"(a), "l"(b));
}

// ============================================================================
// GEMM "NT":  C[m,n] = scale * sum_k A[m,k]*B[n,k]  (+ bias[n])
// A row-major [M,K] (lda), B row-major [N,K] (ldb) -> both K-contiguous.
// Used for: QKV projections, Q@K^T scores, out-projection.
// ============================================================================
__global__ __launch_bounds__(NT, 2)
void gemm_nt(const float* __restrict__ A, const float* __restrict__ B,
             const float* __restrict__ bias, float* __restrict__ C,
             int lda, int ldb, int ldc, int K,
             long aStride, long bStride, long cStride, float scale)
{
    __shared__ float As[BK][BM + 4];
    __shared__ float Bs[BK][BN + 4];

    const int bz  = blockIdx.z;
    A += (long)bz * aStride;
    B += (long)bz * bStride;
    C += (long)bz * cStride;

    const int bm0 = blockIdx.y * BM;
    const int bn0 = blockIdx.x * BN;
    const int tid = threadIdx.x;
    const int tx  = tid & 15;       // m-direction (16)
    const int ty  = tid >> 4;       // n-direction (16)

    unsigned long long acc[8][2];
#pragma unroll
    for (int i = 0; i < 8; i++) { acc[i][0] = 0ULL; acc[i][1] = 0ULL; }

    for (int k0 = 0; k0 < K; k0 += BK) {
        // A tile: 128 rows x 16 k = 512 float4; thread loads 2
#pragma unroll
        for (int r = 0; r < 2; r++) {
            int f   = tid + r * NT;
            int row = f >> 2;
            int kc  = (f & 3) * 4;
            float4 v = *reinterpret_cast<const float4*>(
                &A[(long)(bm0 + row) * lda + k0 + kc]);
            As[kc + 0][row] = v.x; As[kc + 1][row] = v.y;
            As[kc + 2][row] = v.z; As[kc + 3][row] = v.w;
        }
        // B tile: 64 rows x 16 k = 256 float4; thread loads 1
        {
            int row = tid >> 2;
            int kc  = (tid & 3) * 4;
            float4 v = *reinterpret_cast<const float4*>(
                &B[(long)(bn0 + row) * ldb + k0 + kc]);
            Bs[kc + 0][row] = v.x; Bs[kc + 1][row] = v.y;
            Bs[kc + 2][row] = v.z; Bs[kc + 3][row] = v.w;
        }
        __syncthreads();

#pragma unroll
        for (int k = 0; k < BK; k++) {
            float4 a0 = *reinterpret_cast<const float4*>(&As[k][tx * 4]);
            float4 a1 = *reinterpret_cast<const float4*>(&As[k][64 + tx * 4]);
            float4 bv = *reinterpret_cast<const float4*>(&Bs[k][ty * 4]);
            unsigned long long b01 = pack2(bv.x, bv.y);
            unsigned long long b23 = pack2(bv.z, bv.w);
            float av[8] = {a0.x, a0.y, a0.z, a0.w, a1.x, a1.y, a1.z, a1.w};
#pragma unroll
            for (int i = 0; i < 8; i++) {
                unsigned long long ai = pack2(av[i], av[i]);
                ffma2(acc[i][0], ai, b01);
                ffma2(acc[i][1], ai, b23);
            }
        }
        __syncthreads();
    }

    // Epilogue
    float bs0 = 0.f, bs1 = 0.f, bs2 = 0.f, bs3 = 0.f;
    if (bias) {
        float4 bb = *reinterpret_cast<const float4*>(&bias[bn0 + ty * 4]);
        bs0 = bb.x; bs1 = bb.y; bs2 = bb.z; bs3 = bb.w;
    }
#pragma unroll
    for (int i = 0; i < 8; i++) {
        int m = bm0 + (i < 4 ? tx * 4 + i : 64 + tx * 4 + (i - 4));
        float c0, c1, c2, c3;
        unpack2(acc[i][0], c0, c1);
        unpack2(acc[i][1], c2, c3);
        float4 out = make_float4(c0 * scale + bs0, c1 * scale + bs1,
                                 c2 * scale + bs2, c3 * scale + bs3);
        *reinterpret_cast<float4*>(&C[(long)m * ldc + bn0 + ty * 4]) = out;
    }
}

// ============================================================================
// GEMM "NN" with TRANSPOSED store:
//   C[n,m] (!) = sum_k A[m,k]*B[k,n]
// A row-major [M,K] (lda, K-contiguous), B row-major [K,N] (ldb, N-contiguous).
// Output written e-major so the reference's swapaxes+reshape becomes a no-op.
// ============================================================================
__global__ __launch_bounds__(NT, 2)
void gemm_nn_tc(const float* __restrict__ A, const float* __restrict__ B,
                float* __restrict__ C,
                int lda, int ldb, int ldct, int K,
                long aStride, long bStride, long cStride)
{
    __shared__ float As[BK][BM + 4];
    __shared__ float Bs[BK][BN + 4];

    const int bz  = blockIdx.z;
    A += (long)bz * aStride;
    B += (long)bz * bStride;
    C += (long)bz * cStride;

    const int bm0 = blockIdx.y * BM;
    const int bn0 = blockIdx.x * BN;
    const int tid = threadIdx.x;
    const int tx  = tid & 15;
    const int ty  = tid >> 4;

    unsigned long long acc[8][2];
#pragma unroll
    for (int i = 0; i < 8; i++) { acc[i][0] = 0ULL; acc[i][1] = 0ULL; }

    for (int k0 = 0; k0 < K; k0 += BK) {
#pragma unroll
        for (int r = 0; r < 2; r++) {
            int f   = tid + r * NT;
            int row = f >> 2;
            int kc  = (f & 3) * 4;
            float4 v = *reinterpret_cast<const float4*>(
                &A[(long)(bm0 + row) * lda + k0 + kc]);
            As[kc + 0][row] = v.x; As[kc + 1][row] = v.y;
            As[kc + 2][row] = v.z; As[kc + 3][row] = v.w;
        }
        // B tile: [16 k-rows][64 n], n contiguous -> direct coalesced copy
        {
            int kr = tid >> 4;            // 0..15
            int nc = (tid & 15) * 4;      // 0..60
            float4 v = *reinterpret_cast<const float4*>(
                &B[(long)(k0 + kr) * ldb + bn0 + nc]);
            *reinterpret_cast<float4*>(&Bs[kr][nc]) = v;
        }
        __syncthreads();

#pragma unroll
        for (int k = 0; k < BK; k++) {
            float4 a0 = *reinterpret_cast<const float4*>(&As[k][tx * 4]);
            float4 a1 = *reinterpret_cast<const float4*>(&As[k][64 + tx * 4]);
            float4 bv = *reinterpret_cast<const float4*>(&Bs[k][ty * 4]);
            unsigned long long b01 = pack2(bv.x, bv.y);
            unsigned long long b23 = pack2(bv.z, bv.w);
            float av[8] = {a0.x, a0.y, a0.z, a0.w, a1.x, a1.y, a1.z, a1.w};
#pragma unroll
            for (int i = 0; i < 8; i++) {
                unsigned long long ai = pack2(av[i], av[i]);
                ffma2(acc[i][0], ai, b01);
                ffma2(acc[i][1], ai, b23);
            }
        }
        __syncthreads();
    }

    // Transposed store: for each of this thread's 4 n-columns, its 8 m-rows
    // are two contiguous groups of 4 -> two float4 stores per column.
    float c[8][4];
#pragma unroll
    for (int i = 0; i < 8; i++) {
        unpack2(acc[i][0], c[i][0], c[i][1]);
        unpack2(acc[i][1], c[i][2], c[i][3]);
    }
#pragma unroll
    for (int j = 0; j < 4; j++) {
        int n = bn0 + ty * 4 + j;
        float4 lo = make_float4(c[0][j], c[1][j], c[2][j], c[3][j]);
        float4 hi = make_float4(c[4][j], c[5][j], c[6][j], c[7][j]);
        *reinterpret_cast<float4*>(&C[(long)n * ldct + bm0 + tx * 4])      = lo;
        *reinterpret_cast<float4*>(&C[(long)n * ldct + bm0 + 64 + tx * 4]) = hi;
    }
}

// ============================================================================
// Row softmax with mask over S=2048 columns. One block (256 thr) per row.
// ============================================================================
__global__ __launch_bounds__(256)
void softmax_mask(float* __restrict__ S, const int* __restrict__ mask, int cols)
{
    const int row = blockIdx.x;          // 0..8191
    const int b   = row >> 11;           // row / 2048
    float* p = S + (long)row * cols;
    const int* mrow = mask + (long)b * cols;
    const int tid = threadIdx.x;

    float vals[8];
    float mx = -3.4e38f;
#pragma unroll
    for (int i = 0; i < 8; i++) {
        int c = tid + i * 256;
        float v = p[c];
        if (mrow[c] == 0) v = -1e9f;
        vals[i] = v;
        mx = fmaxf(mx, v);
    }

    __shared__ float red[16];
#pragma unroll
    for (int off = 16; off; off >>= 1)
        mx = fmaxf(mx, __shfl_xor_sync(0xffffffffu, mx, off));
    if ((tid & 31) == 0) red[tid >> 5] = mx;
    __syncthreads();
    if (tid < 32) {
        float v = (tid < 8) ? red[tid] : -3.4e38f;
#pragma unroll
        for (int off = 4; off; off >>= 1)
            v = fmaxf(v, __shfl_xor_sync(0xffffffffu, v, off));
        if (tid == 0) red[8] = v;
    }
    __syncthreads();
    mx = red[8];

    float sum = 0.f;
#pragma unroll
    for (int i = 0; i < 8; i++) {
        vals[i] = __expf(vals[i] - mx);
        sum += vals[i];
    }
#pragma unroll
    for (int off = 16; off; off >>= 1)
        sum += __shfl_xor_sync(0xffffffffu, sum, off);
    if ((tid & 31) == 0) red[tid >> 5] = sum;
    __syncthreads();
    if (tid < 32) {
        float v = (tid < 8) ? red[tid] : 0.f;
#pragma unroll
        for (int off = 4; off; off >>= 1)
            v += __shfl_xor_sync(0xffffffffu, v, off);
        if (tid == 0) red[9] = v;
    }
    __syncthreads();
    float inv = 1.0f / red[9];

#pragma unroll
    for (int i = 0; i < 8; i++)
        p[tid + i * 256] = vals[i] * inv;
}

// ============================================================================
// Host launcher
// ============================================================================
extern "C" void kernel_launch(void* const* d_in, const int* in_sizes, int n_in,
                              void* d_out, int out_size)
{
    const float* x    = (const float*)d_in[0];
    const int*   mask = (const int*)  d_in[1];
    const float* Wq   = (const float*)d_in[2];
    const float* bq   = (const float*)d_in[3];
    const float* Wk   = (const float*)d_in[4];
    const float* bk   = (const float*)d_in[5];
    const float* Wv   = (const float*)d_in[6];
    const float* bv   = (const float*)d_in[7];
    const float* Wo   = (const float*)d_in[8];
    const float* bo   = (const float*)d_in[9];
    float* out = (float*)d_out;

    float *Q, *K, *V, *S, *AT;
    cudaGetSymbolAddress((void**)&Q,  g_Q);
    cudaGetSymbolAddress((void**)&K,  g_K);
    cudaGetSymbolAddress((void**)&V,  g_V);
    cudaGetSymbolAddress((void**)&S,  g_S);
    cudaGetSymbolAddress((void**)&AT, g_AT);

    dim3 blk(NT);

    // 1) QKV projections: [8192,4096] x [512,4096]^T  (+bias)
    dim3 g1(ELOC / BN, MROWS / BM, 1);
    gemm_nt<<<g1, blk>>>(x, Wq, bq, Q, DMODEL, DMODEL, ELOC, DMODEL, 0, 0, 0, 1.0f);
    gemm_nt<<<g1, blk>>>(x, Wk, bk, K, DMODEL, DMODEL, ELOC, DMODEL, 0, 0, 0, 1.0f);
    gemm_nt<<<g1, blk>>>(x, Wv, bv, V, DMODEL, DMODEL, ELOC, DMODEL, 0, 0, 0, 1.0f);

    // 2) scores = Q @ K^T / sqrt(128), per batch
    dim3 g2(SEQ / BN, SEQ / BM, BATCH);
    gemm_nt<<<g2, blk>>>(Q, K, nullptr, S, ELOC, ELOC, SEQ, ELOC,
                         (long)SEQ * ELOC, (long)SEQ * ELOC, (long)SEQ * SEQ,
                         0.08838834764831845f);

    // 3) masked softmax over rows
    softmax_mask<<<MROWS, 256>>>(S, mask, SEQ);

    // 4) attnT[b,e,q] = sum_k P[b,q,k] * V[b,k,e]   (stored e-major:
    //    this makes the reference's swapaxes(1,2).reshape a flat no-op)
    dim3 g3(ELOC / BN, SEQ / BM, BATCH);
    gemm_nn_tc<<<g3, blk>>>(S, V, AT, SEQ, ELOC, SEQ, SEQ,
                            (long)SEQ * SEQ, (long)SEQ * ELOC, (long)ELOC * SEQ);

    // 5) out = attn_view @ Wo^T + bo : attn_view flat == g_AT flat,
    //    rows m = b*2048+i at g_AT + m*512  -> single GEMM M=8192,K=512,N=4096
    dim3 g4(DMODEL / BN, MROWS / BM, 1);
    gemm_nt<<<g4, blk>>>(AT, Wo, bo, out, ELOC, ELOC, DMODEL, ELOC, 0, 0, 0, 1.0f);
}

// round 7
// speedup vs baseline: 2.4630x; 2.4630x over previous
#include <cuda_runtime.h>
#include <cuda_bf16.h>

#define BATCH  4
#define SEQ    2048
#define DMODEL 4096
#define ELOC   512
#define MROWS  8192
#define QSCALE 0.08838834764831845f

#define BM 128
#define BN 128
#define BK 32
#define NTH 256

typedef __nv_bfloat16 bf16;
typedef unsigned int u32;

// ---------------- SMEM map (bytes) ----------------
#define SM_BIAS 0                 // 512 B (128 floats)
#define SM_STG  1024
#define ROWB    80                // 32 bf16 (64B) + 16B pad: conflict-free
#define ARRB    (128*ROWB)        // 10240
#define OFF_AH  0
#define OFF_AL  ARRB
#define OFF_BH  (2*ARRB)
#define OFF_BL  (3*ARRB)
#define STGB    (4*ARRB)          // 40960
#define SMEM_TOTAL (SM_STG + 2*STGB)   // 82944
#define EP_OFF  SM_STG            // epilogue f32 tile reuses stage region
#define EPS     132               // floats per epilogue row (128+4 pad)

// ---------------- scratch (static device arrays) ----------------
__device__ bf16  g_xhi [(size_t)MROWS*DMODEL];
__device__ bf16  g_xlo [(size_t)MROWS*DMODEL];
__device__ bf16  g_Wqhi[(size_t)ELOC*DMODEL];
__device__ bf16  g_Wqlo[(size_t)ELOC*DMODEL];
__device__ bf16  g_Wkhi[(size_t)ELOC*DMODEL];
__device__ bf16  g_Wklo[(size_t)ELOC*DMODEL];
__device__ bf16  g_Wvhi[(size_t)ELOC*DMODEL];
__device__ bf16  g_Wvlo[(size_t)ELOC*DMODEL];
__device__ bf16  g_Wohi[(size_t)DMODEL*ELOC];
__device__ bf16  g_Wolo[(size_t)DMODEL*ELOC];
__device__ bf16  g_Qhi [(size_t)MROWS*ELOC];
__device__ bf16  g_Qlo [(size_t)MROWS*ELOC];
__device__ bf16  g_Khi [(size_t)MROWS*ELOC];
__device__ bf16  g_Klo [(size_t)MROWS*ELOC];
__device__ bf16  g_VThi[(size_t)BATCH*ELOC*SEQ];
__device__ bf16  g_VTlo[(size_t)BATCH*ELOC*SEQ];
__device__ float g_S   [(size_t)BATCH*SEQ*SEQ];
__device__ bf16  g_Phi [(size_t)BATCH*SEQ*SEQ];
__device__ bf16  g_Plo [(size_t)BATCH*SEQ*SEQ];
__device__ bf16  g_AThi[(size_t)BATCH*ELOC*SEQ];
__device__ bf16  g_ATlo[(size_t)BATCH*ELOC*SEQ];

// ---------------- helpers ----------------
__device__ __forceinline__ u32 smem_u32(const void* p) {
    u32 a;
    asm("{ .reg .u64 t; cvta.to.shared.u64 t, %1; cvt.u32.u64 %0, t; }"
        : "=r"(a) : "l"(p));
    return a;
}
__device__ __forceinline__ void cpa(u32 d, const void* s) {
    asm volatile("cp.async.cg.shared.global [%0], [%1], 16;" :: "r"(d), "l"(s));
}
__device__ __forceinline__ void cp_commit() {
    asm volatile("cp.async.commit_group;" ::: "memory");
}
template<int N> __device__ __forceinline__ void cp_wait() {
    asm volatile("cp.async.wait_group %0;" :: "n"(N) : "memory");
}
__device__ __forceinline__ void mma_bf16(float* c, const u32* a, u32 b0, u32 b1) {
    asm volatile(
        "mma.sync.aligned.m16n8k16.row.col.f32.bf16.bf16.f32 "
        "{%0,%1,%2,%3}, {%4,%5,%6,%7}, {%8,%9}, {%0,%1,%2,%3};"
        : "+f"(c[0]), "+f"(c[1]), "+f"(c[2]), "+f"(c[3])
        : "r"(a[0]), "r"(a[1]), "r"(a[2]), "r"(a[3]), "r"(b0), "r"(b1));
}
__device__ __forceinline__ u32 pk(bf16 a, bf16 b) {
    return (u32)__bfloat16_as_ushort(a) | ((u32)__bfloat16_as_ushort(b) << 16);
}

// ============================================================================
// HMMA NT GEMM, hi/lo bf16 split, 3 accumulating passes.
// D[m,n] = (sum_k A[m,k]*B[n,k]) * scale + bias[n]
// mode 0: split-bf16 row-major C[m,n]
// mode 1: split-bf16 TRANSPOSED C[n,m], per-batch fold by m0/2048 (V -> VT)
// mode 2: fp32 row-major Cf[m,n]
// ============================================================================
__global__ void __launch_bounds__(NTH, 1)
gemm_mma(const bf16* __restrict__ Ahi, const bf16* __restrict__ Alo,
         const bf16* __restrict__ Bhi, const bf16* __restrict__ Blo,
         int lda, int ldb, int K,
         long long aStr, long long bStr, long long cStr,
         const float* __restrict__ bias, float scale, int mode,
         bf16* __restrict__ Chi, bf16* __restrict__ Clo,
         float* __restrict__ Cf, int ldc)
{
    extern __shared__ char smem[];
    const int tid  = threadIdx.x;
    const int lane = tid & 31;
    const int wid  = tid >> 5;
    const int wm   = wid >> 1;          // 0..3  (m-warp)
    const int wn   = wid & 1;           // 0..1  (n-warp)
    const int g    = lane >> 2;         // groupID 0..7
    const int t    = lane & 3;          // thread-in-group
    const int m0 = blockIdx.y * BM;
    const int n0 = blockIdx.x * BN;
    const int bz = blockIdx.z;

    Ahi += (long long)bz * aStr;  Alo += (long long)bz * aStr;
    Bhi += (long long)bz * bStr;  Blo += (long long)bz * bStr;
    if (Chi) { Chi += (long long)bz * cStr; Clo += (long long)bz * cStr; }
    if (Cf)    Cf += (long long)bz * cStr;

    float* smB = (float*)(smem + SM_BIAS);
    if (tid < 128) smB[tid] = bias ? bias[n0 + tid] : 0.f;

    const u32 sb = smem_u32(smem);
    const bf16* Abh = Ahi + (size_t)m0 * lda;
    const bf16* Abl = Alo + (size_t)m0 * lda;
    const bf16* Bbh = Bhi + (size_t)n0 * ldb;
    const bf16* Bbl = Blo + (size_t)n0 * ldb;

    float acc[2][8][4];
#pragma unroll
    for (int mi = 0; mi < 2; mi++)
#pragma unroll
        for (int ni = 0; ni < 8; ni++)
#pragma unroll
            for (int j = 0; j < 4; j++) acc[mi][ni][j] = 0.f;

    const int nCh = K / BK;

    auto issue = [&](int ch) {
        const u32 stg = sb + SM_STG + (u32)(ch & 1) * STGB;
        const size_t ko = (size_t)ch * BK;
#pragma unroll
        for (int i = 0; i < 2; i++) {
            int idx = tid + i * NTH;
            int r = idx >> 2, cc = idx & 3;
            u32 d = stg + (u32)(r * ROWB + cc * 16);
            size_t ea = (size_t)r * lda + ko + cc * 8;
            size_t eb = (size_t)r * ldb + ko + cc * 8;
            cpa(d + OFF_AH, Abh + ea);
            cpa(d + OFF_AL, Abl + ea);
            cpa(d + OFF_BH, Bbh + eb);
            cpa(d + OFF_BL, Bbl + eb);
        }
    };

    auto compute = [&](int s) {
        const char* stg = smem + SM_STG + s * STGB;
#pragma unroll
        for (int kh = 0; kh < 2; kh++) {
            const int kb = kh * 32;              // k16 byte offset within row
            u32 ah[2][4], al[2][4];
#pragma unroll
            for (int mi = 0; mi < 2; mi++) {
                const int r0 = wm * 32 + mi * 16 + g;
                const char* ph = stg + OFF_AH + kb + t * 4;
                const char* pl = stg + OFF_AL + kb + t * 4;
                ah[mi][0] = *(const u32*)(ph + r0 * ROWB);
                ah[mi][1] = *(const u32*)(ph + (r0 + 8) * ROWB);
                ah[mi][2] = *(const u32*)(ph + r0 * ROWB + 16);
                ah[mi][3] = *(const u32*)(ph + (r0 + 8) * ROWB + 16);
                al[mi][0] = *(const u32*)(pl + r0 * ROWB);
                al[mi][1] = *(const u32*)(pl + (r0 + 8) * ROWB);
                al[mi][2] = *(const u32*)(pl + r0 * ROWB + 16);
                al[mi][3] = *(const u32*)(pl + (r0 + 8) * ROWB + 16);
            }
#pragma unroll
            for (int ni = 0; ni < 8; ni++) {
                const int nr = wn * 64 + ni * 8 + g;
                const char* pb = stg + kb + t * 4 + nr * ROWB;
                u32 bh0 = *(const u32*)(pb + OFF_BH);
                u32 bh1 = *(const u32*)(pb + OFF_BH + 16);
                u32 bl0 = *(const u32*)(pb + OFF_BL);
                u32 bl1 = *(const u32*)(pb + OFF_BL + 16);
#pragma unroll
                for (int mi = 0; mi < 2; mi++) {
                    mma_bf16(acc[mi][ni], ah[mi], bh0, bh1);   // hi*hi
                    mma_bf16(acc[mi][ni], ah[mi], bl0, bl1);   // hi*lo
                    mma_bf16(acc[mi][ni], al[mi], bh0, bh1);   // lo*hi
                }
            }
        }
    };

    issue(0); cp_commit();
#pragma unroll 1
    for (int ch = 0; ch < nCh; ch++) {
        if (ch + 1 < nCh) { issue(ch + 1); cp_commit(); cp_wait<1>(); }
        else              { cp_wait<0>(); }
        __syncthreads();
        compute(ch & 1);
        __syncthreads();
    }

    // ---- Phase A: accumulators (+bias, *scale) -> SMEM f32 tile ----
    float* ep = (float*)(smem + EP_OFF);
#pragma unroll
    for (int mi = 0; mi < 2; mi++) {
        const int r0 = wm * 32 + mi * 16 + g;
#pragma unroll
        for (int ni = 0; ni < 8; ni++) {
            const int c0 = wn * 64 + ni * 8 + 2 * t;
            const float b0 = smB[c0], b1 = smB[c0 + 1];
            ep[r0 * EPS + c0]           = acc[mi][ni][0] * scale + b0;
            ep[r0 * EPS + c0 + 1]       = acc[mi][ni][1] * scale + b1;
            ep[(r0 + 8) * EPS + c0]     = acc[mi][ni][2] * scale + b0;
            ep[(r0 + 8) * EPS + c0 + 1] = acc[mi][ni][3] * scale + b1;
        }
    }
    __syncthreads();

    // ---- Phase B: coalesced global stores ----
    if (mode == 0) {
#pragma unroll 1
        for (int it = 0; it < 32; ++it) {
            int idx = tid + it * NTH;
            int row = idx >> 6, pr = idx & 63;
            float2 v = *(const float2*)&ep[row * EPS + pr * 2];
            bf16 h0 = __float2bfloat16(v.x), h1 = __float2bfloat16(v.y);
            u32 hi = pk(h0, h1);
            u32 lo = pk(__float2bfloat16(v.x - __bfloat162float(h0)),
                        __float2bfloat16(v.y - __bfloat162float(h1)));
            size_t go = (size_t)(m0 + row) * ldc + n0 + pr * 2;
            *(u32*)(Chi + go) = hi;
            *(u32*)(Clo + go) = lo;
        }
    } else if (mode == 1) {
        const size_t cb = (size_t)(m0 >> 11) * ((size_t)ELOC * SEQ);
        const int mloc = m0 & (SEQ - 1);
#pragma unroll 1
        for (int it = 0; it < 32; ++it) {
            int idx = tid + it * NTH;
            int n = idx >> 6, mp = idx & 63;
            float v0 = ep[(mp * 2) * EPS + n];
            float v1 = ep[(mp * 2 + 1) * EPS + n];
            bf16 h0 = __float2bfloat16(v0), h1 = __float2bfloat16(v1);
            u32 hi = pk(h0, h1);
            u32 lo = pk(__float2bfloat16(v0 - __bfloat162float(h0)),
                        __float2bfloat16(v1 - __bfloat162float(h1)));
            size_t go = cb + (size_t)(n0 + n) * ldc + mloc + mp * 2;
            *(u32*)(Chi + go) = hi;
            *(u32*)(Clo + go) = lo;
        }
    } else {
#pragma unroll 1
        for (int it = 0; it < 32; ++it) {
            int idx = tid + it * NTH;
            int row = idx >> 6, pr = idx & 63;
            float2 v = *(const float2*)&ep[row * EPS + pr * 2];
            *(float2*)&Cf[(size_t)(m0 + row) * ldc + n0 + pr * 2] = v;
        }
    }
}

// ---------------- fp32 -> hi/lo bf16 split ----------------
__global__ __launch_bounds__(256)
void split_f32(const float* __restrict__ in, bf16* __restrict__ hi,
               bf16* __restrict__ lo, int n4)
{
    int i = blockIdx.x * 256 + threadIdx.x;
    if (i >= n4) return;
    float4 v = reinterpret_cast<const float4*>(in)[i];
    bf16 h0 = __float2bfloat16(v.x), h1 = __float2bfloat16(v.y);
    bf16 h2 = __float2bfloat16(v.z), h3 = __float2bfloat16(v.w);
    uint2 hp, lp;
    hp.x = pk(h0, h1); hp.y = pk(h2, h3);
    lp.x = pk(__float2bfloat16(v.x - __bfloat162float(h0)),
              __float2bfloat16(v.y - __bfloat162float(h1)));
    lp.y = pk(__float2bfloat16(v.z - __bfloat162float(h2)),
              __float2bfloat16(v.w - __bfloat162float(h3)));
    reinterpret_cast<uint2*>(hi)[i] = hp;
    reinterpret_cast<uint2*>(lo)[i] = lp;
}

// ---------------- masked softmax -> split-bf16 P ----------------
__global__ __launch_bounds__(256)
void softmax_split(const float* __restrict__ S, const int* __restrict__ mask,
                   bf16* __restrict__ Phi, bf16* __restrict__ Plo)
{
    const int row = blockIdx.x;
    const int b   = row >> 11;
    const float* p = S + (size_t)row * SEQ;
    const int* mrow = mask + (size_t)b * SEQ;
    const int tid = threadIdx.x;

    float vals[8];
    float mx = -3.4e38f;
#pragma unroll
    for (int i = 0; i < 8; i++) {
        int c = tid + i * 256;
        float v = p[c];
        if (mrow[c] == 0) v = -1e9f;
        vals[i] = v;
        mx = fmaxf(mx, v);
    }
    __shared__ float red[16];
#pragma unroll
    for (int o = 16; o; o >>= 1) mx = fmaxf(mx, __shfl_xor_sync(~0u, mx, o));
    if ((tid & 31) == 0) red[tid >> 5] = mx;
    __syncthreads();
    if (tid < 32) {
        float v = (tid < 8) ? red[tid] : -3.4e38f;
#pragma unroll
        for (int o = 4; o; o >>= 1) v = fmaxf(v, __shfl_xor_sync(~0u, v, o));
        if (tid == 0) red[8] = v;
    }
    __syncthreads();
    mx = red[8];

    float sum = 0.f;
#pragma unroll
    for (int i = 0; i < 8; i++) { vals[i] = __expf(vals[i] - mx); sum += vals[i]; }
#pragma unroll
    for (int o = 16; o; o >>= 1) sum += __shfl_xor_sync(~0u, sum, o);
    if ((tid & 31) == 0) red[tid >> 5] = sum;
    __syncthreads();
    if (tid < 32) {
        float v = (tid < 8) ? red[tid] : 0.f;
#pragma unroll
        for (int o = 4; o; o >>= 1) v += __shfl_xor_sync(~0u, v, o);
        if (tid == 0) red[9] = v;
    }
    __syncthreads();
    const float inv = 1.0f / red[9];

    bf16* ph = Phi + (size_t)row * SEQ;
    bf16* pl = Plo + (size_t)row * SEQ;
#pragma unroll
    for (int i = 0; i < 8; i++) {
        int c = tid + i * 256;
        float v = vals[i] * inv;
        bf16 h = __float2bfloat16(v);
        ph[c] = h;
        pl[c] = __float2bfloat16(v - __bfloat162float(h));
    }
}

// ============================================================================
extern "C" void kernel_launch(void* const* d_in, const int* in_sizes, int n_in,
                              void* d_out, int out_size)
{
    const float* x    = (const float*)d_in[0];
    const int*   mask = (const int*)  d_in[1];
    const float* Wq   = (const float*)d_in[2];
    const float* bq   = (const float*)d_in[3];
    const float* Wk   = (const float*)d_in[4];
    const float* bk   = (const float*)d_in[5];
    const float* Wv   = (const float*)d_in[6];
    const float* bv   = (const float*)d_in[7];
    const float* Wo   = (const float*)d_in[8];
    const float* bo   = (const float*)d_in[9];
    float* out = (float*)d_out;

    cudaFuncSetAttribute(gemm_mma, cudaFuncAttributeMaxDynamicSharedMemorySize,
                         SMEM_TOTAL);

    bf16 *xhi, *xlo, *Wqh, *Wql, *Wkh, *Wkl, *Wvh, *Wvl, *Woh, *Wol;
    bf16 *Qh, *Ql, *Kh, *Kl, *VTh, *VTl, *Ph, *Pl, *ATh, *ATl;
    float *S;
    cudaGetSymbolAddress((void**)&xhi, g_xhi);  cudaGetSymbolAddress((void**)&xlo, g_xlo);
    cudaGetSymbolAddress((void**)&Wqh, g_Wqhi); cudaGetSymbolAddress((void**)&Wql, g_Wqlo);
    cudaGetSymbolAddress((void**)&Wkh, g_Wkhi); cudaGetSymbolAddress((void**)&Wkl, g_Wklo);
    cudaGetSymbolAddress((void**)&Wvh, g_Wvhi); cudaGetSymbolAddress((void**)&Wvl, g_Wvlo);
    cudaGetSymbolAddress((void**)&Woh, g_Wohi); cudaGetSymbolAddress((void**)&Wol, g_Wolo);
    cudaGetSymbolAddress((void**)&Qh,  g_Qhi);  cudaGetSymbolAddress((void**)&Ql,  g_Qlo);
    cudaGetSymbolAddress((void**)&Kh,  g_Khi);  cudaGetSymbolAddress((void**)&Kl,  g_Klo);
    cudaGetSymbolAddress((void**)&VTh, g_VThi); cudaGetSymbolAddress((void**)&VTl, g_VTlo);
    cudaGetSymbolAddress((void**)&Ph,  g_Phi);  cudaGetSymbolAddress((void**)&Pl,  g_Plo);
    cudaGetSymbolAddress((void**)&ATh, g_AThi); cudaGetSymbolAddress((void**)&ATl, g_ATlo);
    cudaGetSymbolAddress((void**)&S,   g_S);

    // 0) split fp32 inputs into hi/lo bf16
    split_f32<<<MROWS*DMODEL/4/256, 256>>>(x,  xhi, xlo, MROWS*DMODEL/4);
    split_f32<<<ELOC*DMODEL/4/256,  256>>>(Wq, Wqh, Wql, ELOC*DMODEL/4);
    split_f32<<<ELOC*DMODEL/4/256,  256>>>(Wk, Wkh, Wkl, ELOC*DMODEL/4);
    split_f32<<<ELOC*DMODEL/4/256,  256>>>(Wv, Wvh, Wvl, ELOC*DMODEL/4);
    split_f32<<<DMODEL*ELOC/4/256,  256>>>(Wo, Woh, Wol, DMODEL*ELOC/4);

    dim3 blk(NTH);

    // 1) Q/K projections -> split-bf16 row-major [8192,512]
    dim3 g1(ELOC / BN, MROWS / BM, 1);
    gemm_mma<<<g1, blk, SMEM_TOTAL>>>(xhi, xlo, Wqh, Wql, DMODEL, DMODEL, DMODEL,
                                      0, 0, 0, bq, 1.0f, 0, Qh, Ql, nullptr, ELOC);
    gemm_mma<<<g1, blk, SMEM_TOTAL>>>(xhi, xlo, Wkh, Wkl, DMODEL, DMODEL, DMODEL,
                                      0, 0, 0, bk, 1.0f, 0, Kh, Kl, nullptr, ELOC);
    // 2) V projection -> TRANSPOSED split-bf16 VT[b][e][s]
    gemm_mma<<<g1, blk, SMEM_TOTAL>>>(xhi, xlo, Wvh, Wvl, DMODEL, DMODEL, DMODEL,
                                      0, 0, 0, bv, 1.0f, 1, VTh, VTl, nullptr, SEQ);

    // 3) scores = Q·K^T / sqrt(128) -> fp32 S, per batch
    dim3 g2(SEQ / BN, SEQ / BM, BATCH);
    gemm_mma<<<g2, blk, SMEM_TOTAL>>>(Qh, Ql, Kh, Kl, ELOC, ELOC, ELOC,
                                      (long long)SEQ*ELOC, (long long)SEQ*ELOC,
                                      (long long)SEQ*SEQ,
                                      nullptr, QSCALE, 2, nullptr, nullptr, S, SEQ);

    // 4) masked softmax -> split-bf16 P
    softmax_split<<<MROWS, 256>>>(S, mask, Ph, Pl);

    // 5) AT[b][e][q] = sum_s VT[b][e][s]*P[b][q][s] -> split-bf16 [e][q]
    dim3 g3(SEQ / BN, ELOC / BM, BATCH);
    gemm_mma<<<g3, blk, SMEM_TOTAL>>>(VTh, VTl, Ph, Pl, SEQ, SEQ, SEQ,
                                      (long long)ELOC*SEQ, (long long)SEQ*SEQ,
                                      (long long)ELOC*SEQ,
                                      nullptr, 1.0f, 0, ATh, ATl, nullptr, SEQ);

    // 6) out = attn_view·Wo^T + bo ; AT[b] flat == attn_view[b] flat [2048,512]
    dim3 g4(DMODEL / BN, MROWS / BM, 1);
    gemm_mma<<<g4, blk, SMEM_TOTAL>>>(ATh, ATl, Woh, Wol, ELOC, ELOC, ELOC,
                                      0, 0, 0, bo, 1.0f, 2, nullptr, nullptr,
                                      out, DMODEL);
}